// round 1
// baseline (speedup 1.0000x reference)
#include <cuda_runtime.h>

// ============================================================================
// Linear slab model:  z_{n+1} = a*z_n + forcing,  a = (1 - dt*K1) - i*dt*fc
// Parallelized as a segmented linear-recurrence scan:
//   Pass1: per-segment forced response h_t (zero initial state)
//   Pass2: scan  start_{t+1} = A*start_t + h_t,  A = a^SEG_LEN
//   Pass3: re-integrate each segment from its true start, write all steps
// ============================================================================

#define SEG_LEN 120          // multiple of 4 (vector stores) and of nsubsteps=60
#define MAXSEG  262144       // supports nsteps up to ~31.4M
#define SCAN_T  1024

__device__ float2 g_h[MAXSEG];
__device__ float2 g_start[MAXSEG];

__device__ __forceinline__ float2 cmul(float2 a, float2 b) {
    return make_float2(a.x * b.x - a.y * b.y, a.x * b.y + a.y * b.x);
}
// A*z + h (complex)
__device__ __forceinline__ float2 cfma2(float2 A, float2 z, float2 h) {
    return make_float2(fmaf(A.x, z.x, fmaf(-A.y, z.y, h.x)),
                       fmaf(A.x, z.y, fmaf( A.y, z.x, h.y)));
}

struct Consts {
    float c, d, e;     // c = 1 - dt*K1, d = dt*fc, e = dt*K0
    int   ns;          // nsubsteps = 3600/dt
    float inv_ns;
    int   it0;         // t0/dt
};

__device__ __forceinline__ Consts load_consts(const float* pk, const float* fcp,
                                              const int* t0p, const int* dtp) {
    Consts k;
    int   dti = dtp[0];
    float dtf = (float)dti;
    float K0 = expf(pk[0]);
    float K1 = expf(pk[1]);
    k.c = 1.0f - dtf * K1;
    k.d = dtf * fcp[0];
    k.e = dtf * K0;
    k.ns = 3600 / dti;
    k.inv_ns = 1.0f / (float)k.ns;
    k.it0 = t0p[0] / dti;
    return k;
}

// Integrate one segment. WRITE=true stores every step to out (U block, V block).
template <bool WRITE>
__device__ __forceinline__ void run_seg(
    int seg, int nsteps,
    const float* __restrict__ TAx, const float* __restrict__ TAy, int nl,
    Consts k, float& U, float& V, float* __restrict__ out)
{
    const int base = seg * SEG_LEN;
    const int Lt   = min(SEG_LEN, nsteps - base);
    const float c = k.c, d = k.d, e = k.e, inv_ns = k.inv_ns;
    const int ns = k.ns;

    int it  = k.it0 + base;
    int itf = it / ns;
    int r   = it - itf * ns;
    int i1 = min(itf,     nl - 1);
    int i2 = min(itf + 1, nl - 1);
    float Tx0 = TAx[i1], Tx1 = TAx[i2];
    float Ty0 = TAy[i1], Ty1 = TAy[i2];
    float aa   = (float)r * inv_ns;
    float ftax = e * ((1.0f - aa) * Tx0 + aa * Tx1);
    float ftay = e * ((1.0f - aa) * Ty0 + aa * Ty1);
    const float sf = e * inv_ns;
    float dfx = sf * (Tx1 - Tx0);
    float dfy = sf * (Ty1 - Ty0);

    float* outU = out + base;
    float* outV = out + nsteps + base;
    const bool v4 = (((nsteps | Lt) & 3) == 0);  // base % 4 == 0 always (SEG_LEN%4==0)

    int n = 0;
    if (!WRITE || v4) {
        for (; n + 4 <= Lt; n += 4) {
            float ub[4], vb[4];
#pragma unroll
            for (int kk = 0; kk < 4; kk++) {
                float Un = fmaf(c, U, fmaf( d, V, ftax));
                float Vn = fmaf(c, V, fmaf(-d, U, ftay));
                U = Un; V = Vn;
                ub[kk] = U; vb[kk] = V;
                if (++r == ns) {        // warp-uniform: all lanes share (it0 mod ns) phase
                    r = 0; itf++;
                    Tx0 = Tx1; Ty0 = Ty1;
                    int j = min(itf + 1, nl - 1);
                    Tx1 = TAx[j]; Ty1 = TAy[j];
                    ftax = e * Tx0; ftay = e * Ty0;
                    dfx = sf * (Tx1 - Tx0); dfy = sf * (Ty1 - Ty0);
                } else {
                    ftax += dfx; ftay += dfy;
                }
            }
            if (WRITE) {
                *reinterpret_cast<float4*>(outU + n) = make_float4(ub[0], ub[1], ub[2], ub[3]);
                *reinterpret_cast<float4*>(outV + n) = make_float4(vb[0], vb[1], vb[2], vb[3]);
            }
        }
    }
    // scalar remainder (tail or unaligned fallback)
    for (; n < Lt; n++) {
        float Un = fmaf(c, U, fmaf( d, V, ftax));
        float Vn = fmaf(c, V, fmaf(-d, U, ftay));
        U = Un; V = Vn;
        if (WRITE) { outU[n] = U; outV[n] = V; }
        if (++r == ns) {
            r = 0; itf++;
            Tx0 = Tx1; Ty0 = Ty1;
            int j = min(itf + 1, nl - 1);
            Tx1 = TAx[j]; Ty1 = TAy[j];
            ftax = e * Tx0; ftay = e * Ty0;
            dfx = sf * (Tx1 - Tx0); dfy = sf * (Ty1 - Ty0);
        } else {
            ftax += dfx; ftay += dfy;
        }
    }
}

__global__ void k_pass1(const float* __restrict__ pk,
                        const float* __restrict__ TAx, const float* __restrict__ TAy,
                        const float* __restrict__ fcp,
                        const int* __restrict__ t0p, const int* __restrict__ dtp,
                        int nl, int nsteps, int nseg)
{
    int seg = blockIdx.x * blockDim.x + threadIdx.x;
    if (seg >= nseg) return;
    Consts k = load_consts(pk, fcp, t0p, dtp);
    float U = 0.0f, V = 0.0f;
    run_seg<false>(seg, nsteps, TAx, TAy, nl, k, U, V, nullptr);
    g_h[seg] = make_float2(U, V);
}

__global__ void k_scan(const float* __restrict__ pk, const float* __restrict__ fcp,
                       const int* __restrict__ t0p, const int* __restrict__ dtp,
                       int nseg)
{
    __shared__ float2 sP[SCAN_T];
    __shared__ float2 sS[SCAN_T];
    const int tid = threadIdx.x;
    Consts k = load_consts(pk, fcp, t0p, dtp);

    // A = a^SEG_LEN via binary exponentiation
    float2 a = make_float2(k.c, -k.d);
    float2 A = make_float2(1.0f, 0.0f);
    {
        int p = SEG_LEN; float2 b = a;
        while (p) { if (p & 1) A = cmul(A, b); b = cmul(b, b); p >>= 1; }
    }

    const int C   = (nseg + SCAN_T - 1) / SCAN_T;
    const int beg = tid * C;
    const int end = min(beg + C, nseg);
    const int cnt = max(0, end - beg);

    float2 acc = make_float2(0.0f, 0.0f);
    for (int t = beg; t < end; t++) acc = cfma2(A, acc, g_h[t]);

    // P = A^cnt
    float2 P = make_float2(1.0f, 0.0f);
    {
        int p = cnt; float2 b = A;
        while (p) { if (p & 1) P = cmul(P, b); b = cmul(b, b); p >>= 1; }
    }
    sP[tid] = P; sS[tid] = acc;
    __syncthreads();

    // Hillis-Steele inclusive scan of affine operators (z -> P*z + s)
    for (int off = 1; off < SCAN_T; off <<= 1) {
        float2 pP, pS;
        bool has = (tid >= off);
        if (has) { pP = sP[tid - off]; pS = sS[tid - off]; }
        __syncthreads();
        if (has) {
            float2 myP = sP[tid], myS = sS[tid];
            sP[tid] = cmul(myP, pP);
            sS[tid] = cfma2(myP, pS, myS);
        }
        __syncthreads();
    }

    float2 z = (tid > 0) ? sS[tid - 1] : make_float2(0.0f, 0.0f);
    for (int t = beg; t < end; t++) {
        g_start[t] = z;
        z = cfma2(A, z, g_h[t]);
    }
}

__global__ void k_pass3(const float* __restrict__ pk,
                        const float* __restrict__ TAx, const float* __restrict__ TAy,
                        const float* __restrict__ fcp,
                        const int* __restrict__ t0p, const int* __restrict__ dtp,
                        int nl, int nsteps, int nseg, float* __restrict__ out)
{
    int seg = blockIdx.x * blockDim.x + threadIdx.x;
    if (seg >= nseg) return;
    Consts k = load_consts(pk, fcp, t0p, dtp);
    float2 z0 = g_start[seg];
    float U = z0.x, V = z0.y;
    run_seg<true>(seg, nsteps, TAx, TAy, nl, k, U, V, out);
}

extern "C" void kernel_launch(void* const* d_in, const int* in_sizes, int n_in,
                              void* d_out, int out_size)
{
    const float* pk  = (const float*)d_in[0];
    const float* TAx = (const float*)d_in[1];
    const float* TAy = (const float*)d_in[2];
    const float* fcp = (const float*)d_in[3];
    const int*   t0p = (const int*)d_in[4];
    // d_in[5] = t1 (unused: nsteps derived from out_size)
    const int*   dtp = (const int*)d_in[6];

    const int nl     = in_sizes[1];
    const int nsteps = out_size / 2;
    int nseg = (nsteps + SEG_LEN - 1) / SEG_LEN;
    if (nseg > MAXSEG) nseg = MAXSEG;  // capacity guard (not hit for this problem)

    float* out = (float*)d_out;
    const int TB = 256;
    const int GB = (nseg + TB - 1) / TB;

    k_pass1<<<GB, TB>>>(pk, TAx, TAy, fcp, t0p, dtp, nl, nsteps, nseg);
    k_scan<<<1, SCAN_T>>>(pk, fcp, t0p, dtp, nseg);
    k_pass3<<<GB, TB>>>(pk, TAx, TAy, fcp, t0p, dtp, nl, nsteps, nseg, out);
}

// round 2
// speedup vs baseline: 3.8104x; 3.8104x over previous
#include <cuda_runtime.h>

// ============================================================================
// Linear slab model, fully parallel closed-form solution.
//   z_{n+1} = a*z_n + f_n,  a = (1-dt*K1) - i*dt*fc,  f_n linear per interval.
// Within a forcing interval (ns steps, forcing f = p + q*m):
//   z_m = u + v*m + a^m * (z_start - u),  v = q/(1-a), u = (p-v)/(1-a)
// Pipeline:
//   kA: per-interval (u,v) + interval operator (A=a^ns, H); block-wide scan
//   kB: scan of block aggregates (single block)
//   kC: per-interval start state z0, w = z0 - u
//   kD: per-output-step closed-form evaluation, coalesced float4 stores
// ============================================================================

#define SCAN_B 1024
#define MAXI   262144          // max forcing intervals supported
#define NBMAX  (MAXI / SCAN_B) // 256
#define POW_N  256             // a^m table capacity (ns+1 entries needed)

__device__ float4 g_uv[MAXI];     // (u.x,u.y,v.x,v.y)
__device__ float2 g_w[MAXI];      // w = z0 - u (anchored at interval m=0)
__device__ float2 g_prefS[MAXI];  // exclusive affine-scan S within block
__device__ float2 g_prefP[MAXI];  // exclusive affine-scan P within block
__device__ float2 g_aggS[NBMAX];
__device__ float2 g_aggP[NBMAX];
__device__ float2 g_boff[NBMAX];  // state at start of each block

__device__ __forceinline__ float2 cmul(float2 a, float2 b) {
    return make_float2(a.x * b.x - a.y * b.y, a.x * b.y + a.y * b.x);
}
__device__ __forceinline__ float2 cfma2(float2 A, float2 z, float2 h) {
    return make_float2(fmaf(A.x, z.x, fmaf(-A.y, z.y, h.x)),
                       fmaf(A.x, z.y, fmaf( A.y, z.x, h.y)));
}
__device__ __forceinline__ float2 cpow(float2 a, int e) {
    float2 r = make_float2(1.0f, 0.0f);
    while (e) { if (e & 1) r = cmul(r, a); a = cmul(a, a); e >>= 1; }
    return r;
}
__device__ __forceinline__ float2 cinv(float2 a) {
    float s = 1.0f / (a.x * a.x + a.y * a.y);
    return make_float2(a.x * s, -a.y * s);
}

struct Consts {
    float c, d, e;   // c = 1-dt*K1, d = dt*fc, e = dt*K0
    int   ns;        // nsubsteps = 3600/dt
    float inv_ns;
    int   it0;       // t0/dt
};

__device__ __forceinline__ Consts load_consts(const float* pk, const float* fcp,
                                              const int* t0p, const int* dtp) {
    Consts k;
    int   dti = dtp[0];
    float dtf = (float)dti;
    k.c = 1.0f - dtf * expf(pk[1]);
    k.d = dtf * fcp[0];
    k.e = dtf * expf(pk[0]);
    k.ns = 3600 / dti;
    k.inv_ns = 1.0f / (float)k.ns;
    k.it0 = t0p[0] / dti;
    return k;
}

// ---------------- kA: per-interval ops + intra-block affine scan -------------
__global__ void kA(const float* __restrict__ pk,
                   const float* __restrict__ TAx, const float* __restrict__ TAy,
                   const float* __restrict__ fcp,
                   const int* __restrict__ t0p, const int* __restrict__ dtp,
                   int nl, int nsteps)
{
    __shared__ float2 sP[SCAN_B];
    __shared__ float2 sS[SCAN_B];
    const int tid = threadIdx.x;
    const int s   = blockIdx.x * SCAN_B + tid;

    Consts k = load_consts(pk, fcp, t0p, dtp);
    const int j0 = k.it0 / k.ns;
    const int m0 = k.it0 - j0 * k.ns;
    const int NI = (m0 + nsteps + k.ns - 1) / k.ns;

    float2 a      = make_float2(k.c, -k.d);
    float2 inv1ma = cinv(make_float2(1.0f - k.c, k.d));  // 1/(1-a)

    bool   valid = (s < NI);
    float2 Pi = make_float2(1.0f, 0.0f);
    float2 Si = make_float2(0.0f, 0.0f);
    if (valid) {
        int j  = j0 + s;
        int i1 = min(j,     nl - 1);
        int i2 = min(j + 1, nl - 1);
        float Tx0 = TAx[i1], Tx1 = TAx[i2];
        float Ty0 = TAy[i1], Ty1 = TAy[i2];
        float2 p = make_float2(k.e * Tx0, k.e * Ty0);
        float  eq = k.e * k.inv_ns;
        float2 q = make_float2(eq * (Tx1 - Tx0), eq * (Ty1 - Ty0));
        float2 v = cmul(q, inv1ma);
        float2 u = cmul(make_float2(p.x - v.x, p.y - v.y), inv1ma);
        g_uv[s] = make_float4(u.x, u.y, v.x, v.y);

        int   msta = (s == 0) ? m0 : 0;   // first interval may start mid-way
        float2 P   = cpow(a, k.ns - msta);
        float fns = (float)k.ns, fm = (float)msta;
        float2 zend = make_float2(fmaf(v.x, fns, u.x), fmaf(v.y, fns, u.y));
        float2 zsta = make_float2(fmaf(v.x, fm,  u.x), fmaf(v.y, fm,  u.y));
        float2 Ps   = cmul(P, zsta);
        Si = make_float2(zend.x - Ps.x, zend.y - Ps.y);
        Pi = P;
    }
    sP[tid] = Pi; sS[tid] = Si;
    __syncthreads();

    for (int off = 1; off < SCAN_B; off <<= 1) {
        float2 pP, pS;
        bool has = (tid >= off);
        if (has) { pP = sP[tid - off]; pS = sS[tid - off]; }
        __syncthreads();
        if (has) {
            float2 mP = sP[tid], mS = sS[tid];
            sP[tid] = cmul(mP, pP);
            sS[tid] = cfma2(mP, pS, mS);
        }
        __syncthreads();
    }

    if (valid) {
        g_prefS[s] = (tid > 0) ? sS[tid - 1] : make_float2(0.0f, 0.0f);
        g_prefP[s] = (tid > 0) ? sP[tid - 1] : make_float2(1.0f, 0.0f);
    }
    if (tid == SCAN_B - 1) {
        g_aggS[blockIdx.x] = sS[tid];
        g_aggP[blockIdx.x] = sP[tid];
    }
}

// ---------------- kB: scan block aggregates (single block) -------------------
__global__ void kB(const int* __restrict__ dummy, int nsteps,
                   const int* __restrict__ t0p, const int* __restrict__ dtp)
{
    __shared__ float2 sP[NBMAX];
    __shared__ float2 sS[NBMAX];
    const int tid = threadIdx.x;
    int dti = dtp[0];
    int ns  = 3600 / dti;
    int it0 = t0p[0] / dti;
    int m0  = it0 - (it0 / ns) * ns;
    int NI  = (m0 + nsteps + ns - 1) / ns;
    int NB  = (NI + SCAN_B - 1) / SCAN_B;

    float2 Pi = make_float2(1.0f, 0.0f);
    float2 Si = make_float2(0.0f, 0.0f);
    if (tid < NB) { Pi = g_aggP[tid]; Si = g_aggS[tid]; }
    sP[tid] = Pi; sS[tid] = Si;
    __syncthreads();
    for (int off = 1; off < NBMAX; off <<= 1) {
        float2 pP, pS;
        bool has = (tid >= off);
        if (has) { pP = sP[tid - off]; pS = sS[tid - off]; }
        __syncthreads();
        if (has) {
            float2 mP = sP[tid], mS = sS[tid];
            sP[tid] = cmul(mP, pP);
            sS[tid] = cfma2(mP, pS, mS);
        }
        __syncthreads();
    }
    g_boff[tid] = (tid > 0) ? sS[tid - 1] : make_float2(0.0f, 0.0f);
}

// ---------------- kC: per-interval start states ------------------------------
__global__ void kC(const float* __restrict__ pk,
                   const float* __restrict__ fcp,
                   const int* __restrict__ t0p, const int* __restrict__ dtp,
                   int nsteps)
{
    const int s = blockIdx.x * blockDim.x + threadIdx.x;
    Consts k = load_consts(pk, fcp, t0p, dtp);
    const int j0 = k.it0 / k.ns;
    const int m0 = k.it0 - j0 * k.ns;
    const int NI = (m0 + nsteps + k.ns - 1) / k.ns;
    if (s >= NI) return;

    int b = s >> 10;  // SCAN_B = 1024
    float2 z0 = cfma2(g_prefP[s], g_boff[b], g_prefS[s]);
    float4 uv = g_uv[s];
    int msta  = (s == 0) ? m0 : 0;
    // solve z_m = u + v*m + a^m * w with z_{msta} = z0
    float2 num = make_float2(z0.x - fmaf(uv.z, (float)msta, uv.x),
                             z0.y - fmaf(uv.w, (float)msta, uv.y));
    if (msta != 0) {
        float2 a = make_float2(k.c, -k.d);
        num = cmul(num, cinv(cpow(a, msta)));
    }
    g_w[s] = num;
}

// ---------------- kD: per-step closed-form output ----------------------------
__global__ void kD(const float* __restrict__ pk,
                   const float* __restrict__ fcp,
                   const int* __restrict__ t0p, const int* __restrict__ dtp,
                   int nsteps, float* __restrict__ out)
{
    __shared__ float2 spow[POW_N];
    Consts k = load_consts(pk, fcp, t0p, dtp);
    float2 a = make_float2(k.c, -k.d);
    const bool tab = (k.ns < POW_N);
    if (tab) {
        for (int i = threadIdx.x; i <= k.ns; i += blockDim.x)
            spow[i] = cpow(a, i);
    }
    __syncthreads();

    const int t  = blockIdx.x * blockDim.x + threadIdx.x;
    const int n4 = t * 4;
    if (n4 >= nsteps) return;

    const int j0 = k.it0 / k.ns;
    int it = k.it0 + n4;
    int s  = it / k.ns - j0;
    int r  = it % k.ns;

    float4 uv = g_uv[s];
    float2 w  = g_w[s];

    float U[4], V[4];
#pragma unroll
    for (int kk = 0; kk < 4; kk++) {
        int   m  = r + 1;                    // output n is state AFTER the step
        float fm = (float)m;
        float2 base = make_float2(fmaf(uv.z, fm, uv.x), fmaf(uv.w, fm, uv.y));
        float2 pw   = tab ? spow[m] : cpow(a, m);
        float2 z    = cfma2(pw, w, base);
        U[kk] = z.x; V[kk] = z.y;
        if (kk < 3) {                        // advance interval if crossing
            if (++r == k.ns) {
                r = 0;
                s = min(s + 1, MAXI - 1);
                uv = g_uv[s];
                w  = g_w[s];
            }
        }
    }

    const bool full = (n4 + 4 <= nsteps) && ((nsteps & 3) == 0);
    if (full) {
        *reinterpret_cast<float4*>(out + n4)          = make_float4(U[0], U[1], U[2], U[3]);
        *reinterpret_cast<float4*>(out + nsteps + n4) = make_float4(V[0], V[1], V[2], V[3]);
    } else {
        int lim = min(4, nsteps - n4);
        for (int kk = 0; kk < lim; kk++) {
            out[n4 + kk]          = U[kk];
            out[nsteps + n4 + kk] = V[kk];
        }
    }
}

// ---------------- host ------------------------------------------------------
extern "C" void kernel_launch(void* const* d_in, const int* in_sizes, int n_in,
                              void* d_out, int out_size)
{
    const float* pk  = (const float*)d_in[0];
    const float* TAx = (const float*)d_in[1];
    const float* TAy = (const float*)d_in[2];
    const float* fcp = (const float*)d_in[3];
    const int*   t0p = (const int*)d_in[4];
    // d_in[5] = t1 (unused; nsteps derived from out_size)
    const int*   dtp = (const int*)d_in[6];

    const int nl     = in_sizes[1];
    const int nsteps = out_size / 2;
    float* out = (float*)d_out;

    // Interval count depends on device-resident dt/t0 -> launch conservative
    // grids (extra threads are identity/no-ops).
    kA<<<NBMAX, SCAN_B>>>(pk, TAx, TAy, fcp, t0p, dtp, nl, nsteps);
    kB<<<1, NBMAX>>>(t0p, nsteps, t0p, dtp);
    kC<<<NBMAX, SCAN_B>>>(pk, fcp, t0p, dtp, nsteps);

    const int TB = 256;
    const int nthr = (nsteps + 3) / 4;
    const int GB = (nthr + TB - 1) / TB;
    kD<<<GB, TB>>>(pk, fcp, t0p, dtp, nsteps, out);
}

// round 3
// speedup vs baseline: 4.7105x; 1.2362x over previous
#include <cuda_runtime.h>

// ============================================================================
// Linear slab model, closed-form parallel solution.
//   z_{n+1} = a*z_n + f_n,  a = (1-dt*K1) - i*dt*fc,  f_n linear per interval.
// Within a forcing interval (ns steps, forcing f = p + q*m):
//   z_m = u + v*m + a^m * w,   v = q/(1-a), u = (p-v)/(1-a), w = z_0 - u
// kA: per-interval (u,v) + interval affine op; shuffle-based block scan
// kB: scan block aggregates; build consts block g_k + pow table g_pow
// kD: 8 outputs/thread via incremental closed form; coalesced float4 stores
// ============================================================================

#define SCAN_B 1024
#define MAXI   262144
#define NBMAX  (MAXI / SCAN_B)   // 256
#define POW_N  256

__device__ float4 g_uv[MAXI];    // (u.x, u.y, v.x, v.y)
__device__ float4 g_pref[MAXI];  // exclusive scan: (P.x, P.y, S.x, S.y)
__device__ float2 g_aggS[NBMAX];
__device__ float2 g_aggP[NBMAX];
__device__ float2 g_boff[NBMAX]; // state at start of each kA block
__device__ float2 g_pow[POW_N];  // a^m

struct DevK {
    float c, d, e, inv_ns;             // 16B
    int   ns, it0, j0, m0;             // 16B
    unsigned long long magic;          // div-by-ns magic (shift 37)
    int   pad0, pad1;
};
__device__ DevK g_k;

__device__ __forceinline__ float2 cmul(float2 a, float2 b) {
    return make_float2(fmaf(a.x, b.x, -a.y * b.y), fmaf(a.x, b.y, a.y * b.x));
}
__device__ __forceinline__ float2 cfma2(float2 A, float2 z, float2 h) {
    return make_float2(fmaf(A.x, z.x, fmaf(-A.y, z.y, h.x)),
                       fmaf(A.x, z.y, fmaf( A.y, z.x, h.y)));
}
__device__ __forceinline__ float2 cpow(float2 a, int e) {
    float2 r = make_float2(1.0f, 0.0f);
    while (e) { if (e & 1) r = cmul(r, a); a = cmul(a, a); e >>= 1; }
    return r;
}
__device__ __forceinline__ float2 cinv(float2 a) {
    float s = 1.0f / fmaf(a.x, a.x, a.y * a.y);
    return make_float2(a.x * s, -a.y * s);
}

struct Consts { float c, d, e, inv_ns; int ns, it0; };

__device__ __forceinline__ Consts load_consts(const float* pk, const float* fcp,
                                              const int* t0p, const int* dtp) {
    Consts k;
    int   dti = dtp[0];
    float dtf = (float)dti;
    k.c = 1.0f - dtf * expf(pk[1]);
    k.d = dtf * fcp[0];
    k.e = dtf * expf(pk[0]);
    k.ns = 3600 / dti;
    k.inv_ns = 1.0f / (float)k.ns;
    k.it0 = t0p[0] / dti;
    return k;
}

// ---------------- kA: per-interval ops + shuffle-based affine scan -----------
__global__ __launch_bounds__(SCAN_B) void kA(
    const float* __restrict__ pk,
    const float* __restrict__ TAx, const float* __restrict__ TAy,
    const float* __restrict__ fcp,
    const int* __restrict__ t0p, const int* __restrict__ dtp,
    int nl, int nsteps)
{
    __shared__ float2 wAP[32], wAS[32];       // warp aggregates
    __shared__ float4 sInc[SCAN_B];           // per-thread inclusive (P,S)

    const int tid  = threadIdx.x;
    const int lane = tid & 31;
    const int wrp  = tid >> 5;
    const int s    = blockIdx.x * SCAN_B + tid;

    Consts k = load_consts(pk, fcp, t0p, dtp);
    const int j0 = k.it0 / k.ns;
    const int m0 = k.it0 - j0 * k.ns;
    const int NI = (m0 + nsteps + k.ns - 1) / k.ns;

    float2 a      = make_float2(k.c, -k.d);
    float2 inv1ma = cinv(make_float2(1.0f - k.c, k.d));

    float2 P = make_float2(1.0f, 0.0f);
    float2 S = make_float2(0.0f, 0.0f);
    const bool valid = (s < NI);
    if (valid) {
        int j  = j0 + s;
        int i1 = min(j,     nl - 1);
        int i2 = min(j + 1, nl - 1);
        float Tx0 = TAx[i1], Tx1 = TAx[i2];
        float Ty0 = TAy[i1], Ty1 = TAy[i2];
        float2 p = make_float2(k.e * Tx0, k.e * Ty0);
        float  eq = k.e * k.inv_ns;
        float2 q = make_float2(eq * (Tx1 - Tx0), eq * (Ty1 - Ty0));
        float2 v = cmul(q, inv1ma);
        float2 u = cmul(make_float2(p.x - v.x, p.y - v.y), inv1ma);
        g_uv[s] = make_float4(u.x, u.y, v.x, v.y);

        int   msta = (s == 0) ? m0 : 0;
        P = cpow(a, k.ns - msta);
        float fns = (float)k.ns, fm = (float)msta;
        float2 zend = make_float2(fmaf(v.x, fns, u.x), fmaf(v.y, fns, u.y));
        float2 zsta = make_float2(fmaf(v.x, fm,  u.x), fmaf(v.y, fm,  u.y));
        float2 Ps   = cmul(P, zsta);
        S = make_float2(zend.x - Ps.x, zend.y - Ps.y);
    }

    // intra-warp inclusive scan (compose: earlier=prev, later=mine)
    const unsigned full = 0xffffffffu;
#pragma unroll
    for (int off = 1; off < 32; off <<= 1) {
        float pPx = __shfl_up_sync(full, P.x, off);
        float pPy = __shfl_up_sync(full, P.y, off);
        float pSx = __shfl_up_sync(full, S.x, off);
        float pSy = __shfl_up_sync(full, S.y, off);
        if (lane >= off) {
            float2 pP = make_float2(pPx, pPy);
            float2 pS = make_float2(pSx, pSy);
            S = cfma2(P, pS, S);
            P = cmul(P, pP);
        }
    }
    if (lane == 31) { wAP[wrp] = P; wAS[wrp] = S; }
    __syncthreads();
    if (wrp == 0) {
        float2 aP = wAP[lane], aS = wAS[lane];
#pragma unroll
        for (int off = 1; off < 32; off <<= 1) {
            float pPx = __shfl_up_sync(full, aP.x, off);
            float pPy = __shfl_up_sync(full, aP.y, off);
            float pSx = __shfl_up_sync(full, aS.x, off);
            float pSy = __shfl_up_sync(full, aS.y, off);
            if (lane >= off) {
                float2 pP = make_float2(pPx, pPy);
                float2 pS = make_float2(pSx, pSy);
                aS = cfma2(aP, pS, aS);
                aP = cmul(aP, pP);
            }
        }
        wAP[lane] = aP; wAS[lane] = aS;
    }
    __syncthreads();
    if (wrp > 0) {
        float2 oP = wAP[wrp - 1], oS = wAS[wrp - 1];
        S = cfma2(P, oS, S);
        P = cmul(P, oP);
    }
    sInc[tid] = make_float4(P.x, P.y, S.x, S.y);
    __syncthreads();

    if (valid) {
        float4 ex = (tid > 0) ? sInc[tid - 1] : make_float4(1.f, 0.f, 0.f, 0.f);
        g_pref[s] = ex;
    }
    if (tid == SCAN_B - 1) {
        g_aggP[blockIdx.x] = P;
        g_aggS[blockIdx.x] = S;
    }
}

// ---------------- kB: scan aggregates + build g_k / g_pow --------------------
__global__ __launch_bounds__(NBMAX) void kB(
    const float* __restrict__ pk, const float* __restrict__ fcp,
    const int* __restrict__ t0p, const int* __restrict__ dtp,
    int nsteps)
{
    __shared__ float2 sP[NBMAX];
    __shared__ float2 sS[NBMAX];
    const int tid = threadIdx.x;

    Consts k = load_consts(pk, fcp, t0p, dtp);
    float2 a = make_float2(k.c, -k.d);

    // pow table
    for (int i = tid; i <= k.ns && i < POW_N; i += NBMAX)
        g_pow[i] = cpow(a, i);

    // consts block
    if (tid == 0) {
        DevK dk;
        dk.c = k.c; dk.d = k.d; dk.e = k.e; dk.inv_ns = k.inv_ns;
        dk.ns = k.ns; dk.it0 = k.it0;
        dk.j0 = k.it0 / k.ns;
        dk.m0 = k.it0 - dk.j0 * k.ns;
        dk.magic = (1ull << 37) / (unsigned long long)k.ns + 1ull;
        dk.pad0 = dk.pad1 = 0;
        g_k = dk;
    }

    const int m0 = k.it0 - (k.it0 / k.ns) * k.ns;
    const int NI = (m0 + nsteps + k.ns - 1) / k.ns;
    const int NB = (NI + SCAN_B - 1) / SCAN_B;

    float2 Pi = make_float2(1.0f, 0.0f);
    float2 Si = make_float2(0.0f, 0.0f);
    if (tid < NB) { Pi = g_aggP[tid]; Si = g_aggS[tid]; }
    sP[tid] = Pi; sS[tid] = Si;
    __syncthreads();
    for (int off = 1; off < NBMAX; off <<= 1) {
        float2 pP, pS;
        bool has = (tid >= off);
        if (has) { pP = sP[tid - off]; pS = sS[tid - off]; }
        __syncthreads();
        if (has) {
            float2 mP = sP[tid], mS = sS[tid];
            sP[tid] = cmul(mP, pP);
            sS[tid] = cfma2(mP, pS, mS);
        }
        __syncthreads();
    }
    g_boff[tid] = (tid > 0) ? sS[tid - 1] : make_float2(0.0f, 0.0f);
}

// ---------------- kD: 8 outputs/thread, incremental closed form --------------
__global__ __launch_bounds__(256) void kD(int nsteps, float* __restrict__ out)
{
    __shared__ float2 spow[POW_N];

    // load consts (L1-broadcast)
    const float4 kf = *reinterpret_cast<const float4*>(&g_k.c);
    const int4   ki = *reinterpret_cast<const int4*>(&g_k.ns);
    const unsigned long long magic = g_k.magic;
    const float c = kf.x, d = kf.y;
    const int ns = ki.x, it0 = ki.y, j0 = ki.z, m0 = ki.w;
    const float2 a = make_float2(c, -d);

    for (int i = threadIdx.x; i <= ns && i < POW_N; i += blockDim.x)
        spow[i] = g_pow[i];
    __syncthreads();

    const int t  = blockIdx.x * blockDim.x + threadIdx.x;
    const int n0 = t * 8;
    if (n0 >= nsteps) return;

    const int it = it0 + n0;
    const int sg = (int)(((unsigned long long)it * magic) >> 37);  // it / ns
    int r    = it - sg * ns;
    int sidx = sg - j0;

    // reconstruct interval start state from scan
    float4 uv = __ldg(g_uv + sidx);
    float4 pf = __ldg(g_pref + sidx);
    float2 bo = g_boff[sidx >> 10];
    float2 z0 = cfma2(make_float2(pf.x, pf.y), bo, make_float2(pf.z, pf.w));
    float2 w;
    if (sidx == 0 && m0 != 0) {
        w = make_float2(z0.x - fmaf(uv.z, (float)m0, uv.x),
                        z0.y - fmaf(uv.w, (float)m0, uv.y));
        w = cmul(w, cinv(spow[m0]));
    } else {
        w = make_float2(z0.x - uv.x, z0.y - uv.y);
    }

    int   m  = r + 1;
    float fm = (float)m;
    float2 base = make_float2(fmaf(uv.z, fm, uv.x), fmaf(uv.w, fm, uv.y));
    float2 aw   = cmul(spow[m], w);

    const bool vec = (n0 + 8 <= nsteps) && ((nsteps & 3) == 0);
    if (vec) {
        float Ub[4], Vb[4];
#pragma unroll
        for (int kk = 0; kk < 8; kk++) {
            float2 z = make_float2(base.x + aw.x, base.y + aw.y);
            Ub[kk & 3] = z.x; Vb[kk & 3] = z.y;
            if ((kk & 3) == 3) {
                int o = n0 + kk - 3;
                *reinterpret_cast<float4*>(out + o) =
                    make_float4(Ub[0], Ub[1], Ub[2], Ub[3]);
                *reinterpret_cast<float4*>(out + nsteps + o) =
                    make_float4(Vb[0], Vb[1], Vb[2], Vb[3]);
            }
            if (kk < 7) {
                if (m == ns) {           // boundary: z is next interval's start
                    sidx++;
                    uv = __ldg(g_uv + sidx);
                    w  = make_float2(z.x - uv.x, z.y - uv.y);
                    m  = 1;
                    base = make_float2(uv.x + uv.z, uv.y + uv.w);
                    aw   = cmul(a, w);
                } else {
                    m++;
                    base.x += uv.z; base.y += uv.w;
                    aw = cmul(aw, a);
                }
            }
        }
    } else {
        int lim = min(8, nsteps - n0);
        for (int kk = 0; kk < lim; kk++) {
            float2 z = make_float2(base.x + aw.x, base.y + aw.y);
            out[n0 + kk]          = z.x;
            out[nsteps + n0 + kk] = z.y;
            if (m == ns) {
                sidx++;
                uv = __ldg(g_uv + sidx);
                w  = make_float2(z.x - uv.x, z.y - uv.y);
                m  = 1;
                base = make_float2(uv.x + uv.z, uv.y + uv.w);
                aw   = cmul(a, w);
            } else {
                m++;
                base.x += uv.z; base.y += uv.w;
                aw = cmul(aw, a);
            }
        }
    }
}

// ---------------- host ------------------------------------------------------
extern "C" void kernel_launch(void* const* d_in, const int* in_sizes, int n_in,
                              void* d_out, int out_size)
{
    const float* pk  = (const float*)d_in[0];
    const float* TAx = (const float*)d_in[1];
    const float* TAy = (const float*)d_in[2];
    const float* fcp = (const float*)d_in[3];
    const int*   t0p = (const int*)d_in[4];
    // d_in[5] = t1 (unused; nsteps derived from out_size)
    const int*   dtp = (const int*)d_in[6];

    const int nl     = in_sizes[1];
    const int nsteps = out_size / 2;
    float* out = (float*)d_out;

    kA<<<NBMAX, SCAN_B>>>(pk, TAx, TAy, fcp, t0p, dtp, nl, nsteps);
    kB<<<1, NBMAX>>>(pk, fcp, t0p, dtp, nsteps);

    const int TB = 256;
    const int nthr = (nsteps + 7) / 8;
    const int GB = (nthr + TB - 1) / TB;
    kD<<<GB, TB>>>(nsteps, out);
}